// round 1
// baseline (speedup 1.0000x reference)
#include <cuda_runtime.h>
#include <math.h>

#define D     128
#define Mn    128
#define KTAB  64
#define KSEL  32
#define Bq    2048
#define FEW   5
#define DM    256
#define HID   512
#define GATES 2048

// ---------------- scratch (device globals; no allocation) ----------------
__device__ __align__(128) float g_qn[Bq * DM];
__device__ __align__(128) float g_sn[FEW * DM];
__device__ __align__(128) float g_qg[Bq * DM];
__device__ __align__(128) float g_h1[Bq * HID];
__device__ __align__(128) float g_sg[DM];
__device__ __align__(128) float g_sgn[DM];
__device__ __align__(128) float g_vr[GATES];
__device__ __align__(128) float g_qp[(size_t)Bq * GATES];
__device__ __align__(128) float g_gt[(size_t)Bq * GATES];
__device__ __align__(128) float g_c[Bq * HID];
__device__ __align__(128) float g_h[Bq * DM];

__device__ __forceinline__ float wred(float v) {
#pragma unroll
    for (int o = 16; o; o >>= 1) v += __shfl_xor_sync(0xffffffffu, v, o);
    return v;
}
__device__ __forceinline__ float sigmf(float x) { return 1.f / (1.f + expf(-x)); }

// ---------------- neighbor encoder ----------------
// One CTA per (row, branch). Tasks: [0,2B): queries (l then r); [2B, 2B+2*FEW): supports.
__global__ __launch_bounds__(256) void neigh_kernel(
    const int* __restrict__ query, const int* __restrict__ support,
    const int* __restrict__ qlc, const int* __restrict__ qrc,
    const int* __restrict__ slc, const int* __restrict__ src_,
    const int* __restrict__ knn, const float* __restrict__ emb,
    const float* __restrict__ gcn_w, const float* __restrict__ gcn_w_b,
    const float* __restrict__ gcn_b, const float* __restrict__ gate_w,
    const float* __restrict__ gate_b)
{
    __shared__ float s_center[D];
    __shared__ float s_sim[Mn];
    __shared__ int   s_rid[Mn], s_eid[Mn];
    __shared__ int   s_sel[Mn];
    __shared__ float s_havg[2 * D];
    __shared__ float s_struct[D];
    __shared__ float s_knn[D];
    __shared__ int   s_kid[KTAB];
    __shared__ float s_ksim[KTAB];
    __shared__ int   s_ksel[KTAB];
    __shared__ float s_cn;
    __shared__ float s_alpha;

    int task = blockIdx.x;
    const int* conn; int id; float* outp;
    if (task < 2 * Bq) {
        int row = task & (Bq - 1);
        int br  = task >> 11;
        conn = (br ? qrc : qlc) + (size_t)row * Mn * 2;
        id   = query[row * 2 + br];
        outp = g_qn + (size_t)row * DM + br * D;
    } else {
        int t = task - 2 * Bq;
        int br = t / FEW, row = t % FEW;
        conn = (br ? src_ : slc) + (size_t)row * Mn * 2;
        id   = support[row * 2 + br];
        outp = g_sn + (size_t)row * DM + br * D;
    }
    int tid = threadIdx.x, lane = tid & 31, wid = tid >> 5;

    if (tid < D)  s_center[tid] = emb[(size_t)id * D + tid];
    if (tid < Mn) { s_rid[tid] = conn[tid * 2]; s_eid[tid] = conn[tid * 2 + 1]; }
    __syncthreads();

    if (wid == 0) {
        float c0 = s_center[lane], c1 = s_center[lane + 32],
              c2 = s_center[lane + 64], c3 = s_center[lane + 96];
        float s = wred(c0 * c0 + c1 * c1 + c2 * c2 + c3 * c3);
        if (lane == 0) s_cn = sqrtf(s);
    }
    __syncthreads();
    float cn = s_cn;
    float4 cv = ((const float4*)s_center)[lane];

    // cosine sims of center vs ent for all M neighbors (warp per m)
    for (int m = wid; m < Mn; m += 8) {
        float4 ev = ((const float4*)(emb + (size_t)s_eid[m] * D))[lane];
        float dt = ev.x * cv.x + ev.y * cv.y + ev.z * cv.z + ev.w * cv.w;
        float nn = ev.x * ev.x + ev.y * ev.y + ev.z * ev.z + ev.w * ev.w;
        dt = wred(dt); nn = wred(nn);
        if (lane == 0) s_sim[m] = dt / fmaxf(cn * sqrtf(nn), 1e-8f);
    }
    __syncthreads();

    // exact top-K set with jax tie-breaking (lower index wins)
    if (tid < Mn) {
        float v = s_sim[tid]; int r = 0;
        for (int j = 0; j < Mn; j++) {
            float u = s_sim[j];
            r += (u > v) || (u == v && j < tid);
        }
        s_sel[tid] = (r < KSEL);
    }
    __syncthreads();

    // mean of selected [rel, ent] rows (linearity lets us average before matvec)
    {
        int d = tid & (D - 1), vec = tid >> 7;
        float acc = 0.f;
        for (int m = 0; m < Mn; m++) {
            if (s_sel[m]) {
                int ix = vec ? s_eid[m] : s_rid[m];
                acc += emb[(size_t)ix * D + d];
            }
        }
        s_havg[vec * D + d] = acc * (1.f / KSEL);
    }
    __syncthreads();

    // struct = tanh(havg @ gcn_w[d,:]ᵀ + b)   (warp per 16 outputs)
#pragma unroll
    for (int k = 0; k < 16; k++) {
        int dd = wid * 16 + k;
        const float* w = gcn_w + (size_t)dd * 2 * D;
        float a = 0.f;
#pragma unroll
        for (int s = 0; s < 8; s++) a += w[lane + 32 * s] * s_havg[lane + 32 * s];
        a = wred(a);
        if (lane == 0) s_struct[dd] = tanhf(a + gcn_w_b[dd] + gcn_b[dd]);
    }

    // knn branch
    if (tid < KTAB) s_kid[tid] = knn[(size_t)id * KTAB + tid];
    __syncthreads();
    for (int m = wid; m < KTAB; m += 8) {
        float4 ev = ((const float4*)(emb + (size_t)s_kid[m] * D))[lane];
        float dt = ev.x * cv.x + ev.y * cv.y + ev.z * cv.z + ev.w * cv.w;
        float nn = ev.x * ev.x + ev.y * ev.y + ev.z * ev.z + ev.w * ev.w;
        dt = wred(dt); nn = wred(nn);
        if (lane == 0) s_ksim[m] = dt / fmaxf(cn * sqrtf(nn), 1e-8f);
    }
    __syncthreads();
    if (tid < KTAB) {
        float v = s_ksim[tid]; int r = 0;
        for (int j = 0; j < KTAB; j++) {
            float u = s_ksim[j];
            r += (u > v) || (u == v && j < tid);
        }
        s_ksel[tid] = (r < KSEL);
    }
    __syncthreads();
    if (tid < D) {
        float acc = 0.f;
        for (int m = 0; m < KTAB; m++)
            if (s_ksel[m]) acc += emb[(size_t)s_kid[m] * D + tid];
        s_havg[tid] = acc * (1.f / KSEL);   // kent average; krel is pad row == zeros
    }
    __syncthreads();
#pragma unroll
    for (int k = 0; k < 16; k++) {
        int dd = wid * 16 + k;
        const float* w = gcn_w + (size_t)dd * 2 * D + D;  // columns D..2D only
        float a = 0.f;
#pragma unroll
        for (int s = 0; s < 4; s++) a += w[lane + 32 * s] * s_havg[lane + 32 * s];
        a = wred(a);
        if (lane == 0) s_knn[dd] = tanhf(a + gcn_w_b[dd] + gcn_b[dd]);
    }
    __syncthreads();

    if (wid == 0) {
        float a = 0.f;
#pragma unroll
        for (int s = 0; s < 4; s++) {
            a += gate_w[lane + 32 * s]     * s_struct[lane + 32 * s];
            a += gate_w[D + lane + 32 * s] * s_knn[lane + 32 * s];
        }
        a = wred(a);
        if (lane == 0) s_alpha = sigmf(a + gate_b[0]);
    }
    __syncthreads();
    if (tid < D) {
        float al = s_alpha;
        outp[tid] = (1.f - al) * s_struct[tid] + al * s_knn[tid];
    }
}

// ---------------- support encoder (5 rows) + support_g + normalized sg ----------------
__global__ __launch_bounds__(256) void support_kernel(
    const float* __restrict__ p1_w, const float* __restrict__ p1_b,
    const float* __restrict__ p2_w, const float* __restrict__ p2_b,
    const float* __restrict__ ln_g, const float* __restrict__ ln_b)
{
    __shared__ float sx[DM], sh[HID], sz[DM];
    __shared__ float red[8];
    int tid = threadIdx.x, lane = tid & 31, wid = tid >> 5;
    float accg = 0.f;
    for (int r = 0; r < FEW; r++) {
        sx[tid] = g_sn[r * DM + tid];
        __syncthreads();
        for (int u = wid; u < HID; u += 8) {
            const float* w = p1_w + (size_t)u * DM;
            float a = 0.f;
#pragma unroll
            for (int s = 0; s < 8; s++) a += w[lane + 32 * s] * sx[lane + 32 * s];
            a = wred(a);
            if (lane == 0) sh[u] = fmaxf(a + p1_b[u], 0.f);
        }
        __syncthreads();
        for (int u = wid; u < DM; u += 8) {
            const float* w = p2_w + (size_t)u * HID;
            float a = 0.f;
#pragma unroll
            for (int s = 0; s < 16; s++) a += w[lane + 32 * s] * sh[lane + 32 * s];
            a = wred(a);
            if (lane == 0) sz[u] = a + p2_b[u] + sx[u];
        }
        __syncthreads();
        float z = sz[tid];
        float s1 = wred(z);
        if (lane == 0) red[wid] = s1;
        __syncthreads();
        float mu = (red[0] + red[1] + red[2] + red[3] + red[4] + red[5] + red[6] + red[7]) * (1.f / DM);
        __syncthreads();
        float dz = z - mu;
        float s2 = wred(dz * dz);
        if (lane == 0) red[wid] = s2;
        __syncthreads();
        float var = (red[0] + red[1] + red[2] + red[3] + red[4] + red[5] + red[6] + red[7]) * (1.f / (DM - 1));
        float sig = sqrtf(var);
        accg += dz / (sig + 1e-3f) * ln_g[tid] + ln_b[tid];
        __syncthreads();
    }
    float sg = accg * (1.f / FEW);
    g_sg[tid] = sg;
    float s3 = wred(sg * sg);
    if (lane == 0) red[wid] = s3;
    __syncthreads();
    float nrm = sqrtf(red[0] + red[1] + red[2] + red[3] + red[4] + red[5] + red[6] + red[7]);
    g_sgn[tid] = sg / fmaxf(nrm, 1e-12f);
}

// v_r[g] = support_g · w_hh[g, 256:512]  (warp per gate unit)
__global__ __launch_bounds__(256) void vr_kernel(const float* __restrict__ w_hh) {
    int lane = threadIdx.x & 31, wid = threadIdx.x >> 5;
    int g = blockIdx.x * 8 + wid;
    const float* w = w_hh + (size_t)g * HID + DM;
    float a = 0.f;
#pragma unroll
    for (int s = 0; s < 8; s++) a += w[lane + 32 * s] * g_sg[lane + 32 * s];
    a = wred(a);
    if (lane == 0) g_vr[g] = a;
}

// ---------------- generic SGEMM: C[M,N] = A[M,K] · B[N,K]ᵀ + epilogue ----------------
#define BM 128
#define BN 128
#define BK 16
__global__ __launch_bounds__(256) void sgemm_tn(
    const float* __restrict__ A, int lda,
    const float* __restrict__ B, int ldb,
    float* __restrict__ C, int N, int K,
    const float* __restrict__ bias0, const float* __restrict__ bias1,
    const float* __restrict__ addmat, const float* __restrict__ addrow,
    int relu)
{
    __shared__ float As[BK][BM + 4];
    __shared__ float Bs[BK][BN + 4];
    int tid = threadIdx.x;
    int bm = blockIdx.y * BM, bn = blockIdx.x * BN;
    int tm = (tid >> 4) * 8, tn = (tid & 15) * 8;
    int ar = tid >> 2;
    int ac = (tid & 3) * 4;
    const float* Ap = A + (size_t)(bm + ar) * lda + ac;
    const float* Bp = B + (size_t)(bn + ar) * ldb + ac;

    float acc[8][8];
#pragma unroll
    for (int i = 0; i < 8; i++)
#pragma unroll
        for (int j = 0; j < 8; j++) acc[i][j] = 0.f;

    for (int k0 = 0; k0 < K; k0 += BK) {
        float4 a0 = *(const float4*)(Ap + k0);
        float4 a1 = *(const float4*)(Ap + (size_t)64 * lda + k0);
        float4 b0 = *(const float4*)(Bp + k0);
        float4 b1 = *(const float4*)(Bp + (size_t)64 * ldb + k0);
        __syncthreads();
        As[ac + 0][ar] = a0.x; As[ac + 1][ar] = a0.y; As[ac + 2][ar] = a0.z; As[ac + 3][ar] = a0.w;
        As[ac + 0][ar + 64] = a1.x; As[ac + 1][ar + 64] = a1.y; As[ac + 2][ar + 64] = a1.z; As[ac + 3][ar + 64] = a1.w;
        Bs[ac + 0][ar] = b0.x; Bs[ac + 1][ar] = b0.y; Bs[ac + 2][ar] = b0.z; Bs[ac + 3][ar] = b0.w;
        Bs[ac + 0][ar + 64] = b1.x; Bs[ac + 1][ar + 64] = b1.y; Bs[ac + 2][ar + 64] = b1.z; Bs[ac + 3][ar + 64] = b1.w;
        __syncthreads();
#pragma unroll
        for (int kk = 0; kk < BK; kk++) {
            float a[8], b[8];
            *(float4*)(a)     = *(const float4*)&As[kk][tm];
            *(float4*)(a + 4) = *(const float4*)&As[kk][tm + 4];
            *(float4*)(b)     = *(const float4*)&Bs[kk][tn];
            *(float4*)(b + 4) = *(const float4*)&Bs[kk][tn + 4];
#pragma unroll
            for (int i = 0; i < 8; i++)
#pragma unroll
                for (int j = 0; j < 8; j++)
                    acc[i][j] += a[i] * b[j];
        }
    }
#pragma unroll
    for (int i = 0; i < 8; i++) {
        size_t m = (size_t)(bm + tm + i);
        float v[8];
#pragma unroll
        for (int j = 0; j < 8; j++) {
            int n = bn + tn + j;
            float x = acc[i][j];
            if (bias0)  x += bias0[n];
            if (bias1)  x += bias1[n];
            if (addrow) x += addrow[n];
            v[j] = x;
        }
        if (addmat) {
            const float4* am = (const float4*)(addmat + m * N + bn + tn);
            float4 m0 = am[0], m1 = am[1];
            v[0] += m0.x; v[1] += m0.y; v[2] += m0.z; v[3] += m0.w;
            v[4] += m1.x; v[5] += m1.y; v[6] += m1.z; v[7] += m1.w;
        }
        if (relu) {
#pragma unroll
            for (int j = 0; j < 8; j++) v[j] = fmaxf(v[j], 0.f);
        }
        float4* cp = (float4*)(C + m * N + bn + tn);
        cp[0] = make_float4(v[0], v[1], v[2], v[3]);
        cp[1] = make_float4(v[4], v[5], v[6], v[7]);
    }
}

// layernorm over g_qg rows, in place
__global__ __launch_bounds__(256) void ln_kernel(const float* __restrict__ ln_g,
                                                 const float* __restrict__ ln_b) {
    __shared__ float red[8];
    int row = blockIdx.x, tid = threadIdx.x, lane = tid & 31, wid = tid >> 5;
    float z = g_qg[(size_t)row * DM + tid];
    float s1 = wred(z);
    if (lane == 0) red[wid] = s1;
    __syncthreads();
    float mu = (red[0] + red[1] + red[2] + red[3] + red[4] + red[5] + red[6] + red[7]) * (1.f / DM);
    __syncthreads();
    float dz = z - mu;
    float s2 = wred(dz * dz);
    if (lane == 0) red[wid] = s2;
    __syncthreads();
    float sig = sqrtf((red[0] + red[1] + red[2] + red[3] + red[4] + red[5] + red[6] + red[7]) * (1.f / (DM - 1)));
    g_qg[(size_t)row * DM + tid] = dz / (sig + 1e-3f) * ln_g[tid] + ln_b[tid];
}

// LSTM gates: c/h update; h = query_g + h_[:, :256]
__global__ __launch_bounds__(256) void gate_kernel(const float* __restrict__ G, int first) {
    int idx = blockIdx.x * 256 + threadIdx.x;
    int row = idx >> 9, u = idx & 511;
    const float* g = G + (size_t)row * GATES;
    float iv = g[u], fv = g[HID + u], gv = g[2 * HID + u], ov = g[3 * HID + u];
    float c = first ? 0.f : g_c[idx];
    c = sigmf(fv) * c + sigmf(iv) * tanhf(gv);
    g_c[idx] = c;
    float h_ = sigmf(ov) * tanhf(c);
    if (u < DM) g_h[(size_t)row * DM + u] = g_qg[(size_t)row * DM + u] + h_;
}

// out[row] = (h / max(||h||,1e-12)) · sg_normalized
__global__ __launch_bounds__(256) void final_kernel(float* __restrict__ out) {
    int lane = threadIdx.x & 31, wid = threadIdx.x >> 5;
    int row = blockIdx.x * 8 + wid;
    const float* h = g_h + (size_t)row * DM;
    float ss = 0.f, dt = 0.f;
#pragma unroll
    for (int s = 0; s < 8; s++) {
        float v = h[lane + 32 * s];
        ss += v * v;
        dt += v * g_sgn[lane + 32 * s];
    }
    ss = wred(ss); dt = wred(dt);
    if (lane == 0) out[row] = dt / fmaxf(sqrtf(ss), 1e-12f);
}

// ---------------- host ----------------
extern "C" void kernel_launch(void* const* d_in, const int* in_sizes, int n_in,
                              void* d_out, int out_size) {
    const int*   query   = (const int*)d_in[0];
    const int*   support = (const int*)d_in[1];
    const int*   qlc     = (const int*)d_in[2];
    const int*   qrc     = (const int*)d_in[4];
    const int*   slc     = (const int*)d_in[6];
    const int*   src_    = (const int*)d_in[8];
    const int*   knn     = (const int*)d_in[10];
    const float* emb     = (const float*)d_in[11];
    const float* gcn_w   = (const float*)d_in[12];
    const float* gcn_w_b = (const float*)d_in[13];
    const float* gcn_b   = (const float*)d_in[14];
    const float* gate_w  = (const float*)d_in[15];
    const float* gate_b  = (const float*)d_in[16];
    const float* p1_w    = (const float*)d_in[17];
    const float* p1_b    = (const float*)d_in[18];
    const float* p2_w    = (const float*)d_in[19];
    const float* p2_b    = (const float*)d_in[20];
    const float* ln_g    = (const float*)d_in[21];
    const float* ln_b    = (const float*)d_in[22];
    const float* w_ih    = (const float*)d_in[23];
    const float* w_hh    = (const float*)d_in[24];
    const float* b_ih    = (const float*)d_in[25];
    const float* b_hh    = (const float*)d_in[26];
    float* out = (float*)d_out;

    float *qn, *qg, *h1, *vr, *qp, *gt, *hh;
    cudaGetSymbolAddress((void**)&qn, g_qn);
    cudaGetSymbolAddress((void**)&qg, g_qg);
    cudaGetSymbolAddress((void**)&h1, g_h1);
    cudaGetSymbolAddress((void**)&vr, g_vr);
    cudaGetSymbolAddress((void**)&qp, g_qp);
    cudaGetSymbolAddress((void**)&gt, g_gt);
    cudaGetSymbolAddress((void**)&hh, g_h);

    // 1) neighbor encoders -> g_qn [2048,256], g_sn [5,256]
    neigh_kernel<<<2 * Bq + 2 * FEW, 256>>>(query, support, qlc, qrc, slc, src_,
                                            knn, emb, gcn_w, gcn_w_b, gcn_b, gate_w, gate_b);
    // 2) support path: support_g, normalized sg, v_r
    support_kernel<<<1, 256>>>(p1_w, p1_b, p2_w, p2_b, ln_g, ln_b);
    vr_kernel<<<GATES / 8, 256>>>(w_hh);
    // 3) query support-encoder: h1 = relu(qn @ p1ᵀ + b); qg = h1 @ p2ᵀ + b + qn; LN
    sgemm_tn<<<dim3(HID / BN, Bq / BM), 256>>>(qn, DM, p1_w, DM, h1, HID, DM,
                                               p1_b, nullptr, nullptr, nullptr, 1);
    sgemm_tn<<<dim3(DM / BN, Bq / BM), 256>>>(h1, HID, p2_w, HID, qg, DM, HID,
                                              p2_b, nullptr, qn, nullptr, 0);
    ln_kernel<<<Bq, 256>>>(ln_g, ln_b);
    // 4) LSTM: Qp once, then 3 recurrent GEMMs + gates
    sgemm_tn<<<dim3(GATES / BN, Bq / BM), 256>>>(qg, DM, w_ih, DM, qp, GATES, DM,
                                                 b_ih, b_hh, nullptr, nullptr, 0);
    gate_kernel<<<Bq * HID / 256, 256>>>(qp, 1);
    for (int t = 1; t < 4; t++) {
        sgemm_tn<<<dim3(GATES / BN, Bq / BM), 256>>>(hh, DM, w_hh, HID, gt, GATES, DM,
                                                     nullptr, nullptr, qp, vr, 0);
        gate_kernel<<<Bq * HID / 256, 256>>>(gt, 0);
    }
    // 5) normalized dot with sg
    final_kernel<<<Bq / 8, 256>>>(out);
}

// round 2
// speedup vs baseline: 1.3655x; 1.3655x over previous
#include <cuda_runtime.h>
#include <math.h>

#define D     128
#define Mn    128
#define KTAB  64
#define KSEL  32
#define Bq    2048
#define FEW   5
#define DM    256
#define HID   512
#define GATES 2048
#define NTASK (2 * Bq + 2 * FEW)   // 4106
#define TPAD  4160                 // padded task rows for GEMM

typedef unsigned long long ull;

// ---------------- scratch (device globals; no allocation) ----------------
__device__ __align__(128) float g_hs[TPAD * DM];     // [rel_avg | ent_avg]
__device__ __align__(128) float g_hk[TPAD * D];      // knn ent avg
__device__ __align__(128) float g_c1[TPAD * D];      // struct pre-activation
__device__ __align__(128) float g_c2[TPAD * D];      // knn pre-activation
__device__ __align__(128) float g_qn[Bq * DM];
__device__ __align__(128) float g_sn[FEW * DM];
__device__ __align__(128) float g_act[Bq * HID];
__device__ __align__(128) float g_qg[Bq * DM];
__device__ __align__(128) float g_sg[DM];
__device__ __align__(128) float g_sgn[DM];
__device__ __align__(128) float g_vr[GATES];
__device__ __align__(128) float g_qp[(size_t)Bq * GATES];
__device__ __align__(128) float g_cst[Bq * HID];
__device__ __align__(128) float g_ha[Bq * DM];
__device__ __align__(128) float g_hb[Bq * DM];

__device__ __forceinline__ float wred(float v) {
#pragma unroll
    for (int o = 16; o; o >>= 1) v += __shfl_xor_sync(0xffffffffu, v, o);
    return v;
}
__device__ __forceinline__ float sigmf(float x) { return 1.f / (1.f + expf(-x)); }

__device__ __forceinline__ ull pack2(float x) {
    ull r;
    asm("mov.b64 %0, {%1, %1};" : "=l"(r) : "r"(__float_as_uint(x)));
    return r;
}
__device__ __forceinline__ void dfma(ull& d, ull a, ull b) {
    asm("fma.rn.f32x2 %0, %1, %2, %0;" : "+l"(d) : "l"(a), "l"(b));
}
__device__ __forceinline__ float2 unpack2(ull v) {
    unsigned lo, hi;
    asm("mov.b64 {%0, %1}, %2;" : "=r"(lo), "=r"(hi) : "l"(v));
    float2 f; f.x = __uint_as_float(lo); f.y = __uint_as_float(hi);
    return f;
}
__device__ __forceinline__ int permg(int n) { return (n & 3) * 512 + (n >> 2); }

// ---------------- neighbor gather: sims + topk + selected means ----------------
__global__ __launch_bounds__(256) void neigh_gather(
    const int* __restrict__ query, const int* __restrict__ support,
    const int* __restrict__ qlc, const int* __restrict__ qrc,
    const int* __restrict__ slc, const int* __restrict__ src_,
    const int* __restrict__ knn, const float* __restrict__ emb)
{
    __shared__ float s_center[D];
    __shared__ int   s_rid[Mn], s_eid[Mn];
    __shared__ float s_sim[Mn];
    __shared__ int   s_kid[KTAB];
    __shared__ float s_ksim[KTAB];
    __shared__ int   s_selr[KSEL], s_sele[KSEL], s_kselv[KSEL];
    __shared__ int   s_cnt, s_kcnt;
    __shared__ float s_cn;

    int task = blockIdx.x;
    const int* conn; int id;
    if (task < 2 * Bq) {
        int row = task & (Bq - 1);
        int br  = task >> 11;
        conn = (br ? qrc : qlc) + (size_t)row * Mn * 2;
        id   = query[row * 2 + br];
    } else {
        int t = task - 2 * Bq;
        int br = t / FEW, row = t % FEW;
        conn = (br ? src_ : slc) + (size_t)row * Mn * 2;
        id   = support[row * 2 + br];
    }
    int tid = threadIdx.x, lane = tid & 31, wid = tid >> 5;
    if (tid == 0) { s_cnt = 0; s_kcnt = 0; }
    if (tid < D)  s_center[tid] = emb[(size_t)id * D + tid];
    if (tid < Mn) { s_rid[tid] = conn[tid * 2]; s_eid[tid] = conn[tid * 2 + 1]; }
    if (tid >= 192) s_kid[tid - 192] = knn[(size_t)id * KTAB + (tid - 192)];
    __syncthreads();

    if (wid == 0) {
        float c0 = s_center[lane], c1 = s_center[lane + 32],
              c2 = s_center[lane + 64], c3 = s_center[lane + 96];
        float s = wred(c0 * c0 + c1 * c1 + c2 * c2 + c3 * c3);
        if (lane == 0) s_cn = sqrtf(s);
    }
    __syncthreads();
    float cn = s_cn;
    float4 cv = ((const float4*)s_center)[lane];

    // ent sims: warp handles 16 m, groups of 4 with interleaved reductions
#pragma unroll
    for (int g = 0; g < 4; g++) {
        int m = wid * 16 + g * 4;
        float dt[4], nn[4];
#pragma unroll
        for (int t = 0; t < 4; t++) {
            float4 ev = ((const float4*)(emb + (size_t)s_eid[m + t] * D))[lane];
            dt[t] = ev.x * cv.x + ev.y * cv.y + ev.z * cv.z + ev.w * cv.w;
            nn[t] = ev.x * ev.x + ev.y * ev.y + ev.z * ev.z + ev.w * ev.w;
        }
#pragma unroll
        for (int o = 16; o; o >>= 1) {
#pragma unroll
            for (int t = 0; t < 4; t++) {
                dt[t] += __shfl_xor_sync(0xffffffffu, dt[t], o);
                nn[t] += __shfl_xor_sync(0xffffffffu, nn[t], o);
            }
        }
        if (lane == 0) {
#pragma unroll
            for (int t = 0; t < 4; t++)
                s_sim[m + t] = dt[t] / fmaxf(cn * sqrtf(nn[t]), 1e-8f);
        }
    }
    // knn sims: warp handles 8
#pragma unroll
    for (int g = 0; g < 2; g++) {
        int m = wid * 8 + g * 4;
        float dt[4], nn[4];
#pragma unroll
        for (int t = 0; t < 4; t++) {
            float4 ev = ((const float4*)(emb + (size_t)s_kid[m + t] * D))[lane];
            dt[t] = ev.x * cv.x + ev.y * cv.y + ev.z * cv.z + ev.w * cv.w;
            nn[t] = ev.x * ev.x + ev.y * ev.y + ev.z * ev.z + ev.w * ev.w;
        }
#pragma unroll
        for (int o = 16; o; o >>= 1) {
#pragma unroll
            for (int t = 0; t < 4; t++) {
                dt[t] += __shfl_xor_sync(0xffffffffu, dt[t], o);
                nn[t] += __shfl_xor_sync(0xffffffffu, nn[t], o);
            }
        }
        if (lane == 0) {
#pragma unroll
            for (int t = 0; t < 4; t++)
                s_ksim[m + t] = dt[t] / fmaxf(cn * sqrtf(nn[t]), 1e-8f);
        }
    }
    __syncthreads();

    // exact top-K sets (jax tie semantics: lower index wins) + compaction
    if (tid < Mn) {
        float v = s_sim[tid]; int r = 0;
        for (int j = 0; j < Mn; j++) {
            float u = s_sim[j];
            r += (u > v) || (u == v && j < tid);
        }
        if (r < KSEL) {
            int p = atomicAdd(&s_cnt, 1);
            s_selr[p] = s_rid[tid];
            s_sele[p] = s_eid[tid];
        }
    } else if (tid < Mn + KTAB) {
        int m = tid - Mn;
        float v = s_ksim[m]; int r = 0;
        for (int j = 0; j < KTAB; j++) {
            float u = s_ksim[j];
            r += (u > v) || (u == v && j < m);
        }
        if (r < KSEL) {
            int p = atomicAdd(&s_kcnt, 1);
            s_kselv[p] = s_kid[m];
        }
    }
    __syncthreads();

    // means of selected rows (unrolled, full MLP)
    int d = tid & (D - 1);
    float acc = 0.f;
    if (tid < D) {
#pragma unroll 8
        for (int i = 0; i < KSEL; i++) acc += emb[(size_t)s_selr[i] * D + d];
        g_hs[(size_t)task * DM + d] = acc * (1.f / KSEL);
        float ak = 0.f;
#pragma unroll 8
        for (int i = 0; i < KSEL; i++) ak += emb[(size_t)s_kselv[i] * D + d];
        g_hk[(size_t)task * D + d] = ak * (1.f / KSEL);
    } else {
#pragma unroll 8
        for (int i = 0; i < KSEL; i++) acc += emb[(size_t)s_sele[i] * D + d];
        g_hs[(size_t)task * DM + D + d] = acc * (1.f / KSEL);
    }
}

// ---------------- combine: tanh + gate + scatter to qn/sn ----------------
__global__ __launch_bounds__(256) void combine_kernel(
    const float* __restrict__ gcn_w_b, const float* __restrict__ gcn_b,
    const float* __restrict__ gate_w, const float* __restrict__ gate_b)
{
    int lane = threadIdx.x & 31, wid = threadIdx.x >> 5;
    int t = blockIdx.x * 8 + wid;
    if (t >= NTASK) return;
    int c = lane * 4;
    float4 c1 = *(const float4*)(g_c1 + (size_t)t * D + c);
    float4 c2 = *(const float4*)(g_c2 + (size_t)t * D + c);
    float4 wb = *(const float4*)(gcn_w_b + c);
    float4 gb = *(const float4*)(gcn_b + c);
    float s0 = tanhf(c1.x + wb.x + gb.x), s1 = tanhf(c1.y + wb.y + gb.y);
    float s2 = tanhf(c1.z + wb.z + gb.z), s3 = tanhf(c1.w + wb.w + gb.w);
    float k0 = tanhf(c2.x + wb.x + gb.x), k1 = tanhf(c2.y + wb.y + gb.y);
    float k2 = tanhf(c2.z + wb.z + gb.z), k3 = tanhf(c2.w + wb.w + gb.w);
    float4 gws = *(const float4*)(gate_w + c);
    float4 gwk = *(const float4*)(gate_w + D + c);
    float a = gws.x * s0 + gws.y * s1 + gws.z * s2 + gws.w * s3
            + gwk.x * k0 + gwk.y * k1 + gwk.z * k2 + gwk.w * k3;
    a = wred(a);
    float al = sigmf(a + gate_b[0]);
    float4 o;
    o.x = (1.f - al) * s0 + al * k0;
    o.y = (1.f - al) * s1 + al * k1;
    o.z = (1.f - al) * s2 + al * k2;
    o.w = (1.f - al) * s3 + al * k3;
    float* dst;
    if (t < Bq)            dst = g_qn + (size_t)t * DM + c;
    else if (t < 2 * Bq)   dst = g_qn + (size_t)(t - Bq) * DM + D + c;
    else if (t < 2 * Bq + FEW) dst = g_sn + (size_t)(t - 2 * Bq) * DM + c;
    else                   dst = g_sn + (size_t)(t - 2 * Bq - FEW) * DM + D + c;
    *(float4*)dst = o;
}

// ---------------- templated FFMA2 SGEMM: C[M,N] = A[M,K] · B[N,K]ᵀ ----------------
// MODE 0: relu(acc+bias0) -> C           (h1)
// MODE 1: acc+bias0+addmat -> C          (p2, residual)
// MODE 2: LSTM first step (B rows gate-permuted; stores qp, c, h)
// MODE 3: LSTM recurrent step (adds qp+vr; updates c; writes h)
// MODE 4: plain store; blockIdx.z selects operand set (gcn dual GEMM)
template<int BM, int MODE>
__global__ __launch_bounds__(256) void sgemm(
    const float* __restrict__ A, int lda,
    const float* __restrict__ B, int ldb,
    float* __restrict__ C, int N, int K,
    const float* __restrict__ bias0,
    const float* __restrict__ addmat,
    float* __restrict__ qp, const float* __restrict__ vr,
    const float* __restrict__ bih, const float* __restrict__ bhh,
    float* __restrict__ cst, const float* __restrict__ qg,
    float* __restrict__ hout,
    const float* __restrict__ A2, int lda2,
    const float* __restrict__ B2, int K2, float* __restrict__ C2)
{
    if (MODE == 4 && blockIdx.z == 1) { A = A2; lda = lda2; B = B2; K = K2; C = C2; }
    constexpr int TM = BM / 16;
    __shared__ float As[16][BM + 4];
    __shared__ float Bs[16][132];
    int tid = threadIdx.x;
    int bm = blockIdx.y * BM, bn = blockIdx.x * 128;
    int tm = (tid >> 4) * TM, tn = (tid & 15) * 8;
    int ar = tid >> 2, ac = (tid & 3) * 4;

    int br0 = bn + ar, br1 = bn + ar + 64;
    if (MODE == 2 || MODE == 3) { br0 = permg(br0); br1 = permg(br1); }
    const float* Ap  = A + (size_t)(bm + ar) * lda + ac;
    const float* Bp0 = B + (size_t)br0 * ldb + ac;
    const float* Bp1 = B + (size_t)br1 * ldb + ac;

    ull acc2[TM][4];
#pragma unroll
    for (int i = 0; i < TM; i++)
#pragma unroll
        for (int j = 0; j < 4; j++) acc2[i][j] = 0ULL;

    for (int k0 = 0; k0 < K; k0 += 16) {
        float4 a0 = *(const float4*)(Ap + k0);
        float4 a1;
        if (BM == 128) a1 = *(const float4*)(Ap + (size_t)64 * lda + k0);
        float4 b0 = *(const float4*)(Bp0 + k0);
        float4 b1 = *(const float4*)(Bp1 + k0);
        __syncthreads();
        As[ac + 0][ar] = a0.x; As[ac + 1][ar] = a0.y; As[ac + 2][ar] = a0.z; As[ac + 3][ar] = a0.w;
        if (BM == 128) {
            As[ac + 0][ar + 64] = a1.x; As[ac + 1][ar + 64] = a1.y;
            As[ac + 2][ar + 64] = a1.z; As[ac + 3][ar + 64] = a1.w;
        }
        Bs[ac + 0][ar] = b0.x; Bs[ac + 1][ar] = b0.y; Bs[ac + 2][ar] = b0.z; Bs[ac + 3][ar] = b0.w;
        Bs[ac + 0][ar + 64] = b1.x; Bs[ac + 1][ar + 64] = b1.y;
        Bs[ac + 2][ar + 64] = b1.z; Bs[ac + 3][ar + 64] = b1.w;
        __syncthreads();
#pragma unroll
        for (int kk = 0; kk < 16; kk++) {
            float av[TM];
            *(float4*)av = *(const float4*)&As[kk][tm];
            if (TM == 8) *(float4*)(av + 4) = *(const float4*)&As[kk][tm + 4];
            ulonglong2 p01 = *(const ulonglong2*)&Bs[kk][tn];
            ulonglong2 p23 = *(const ulonglong2*)&Bs[kk][tn + 4];
            ull bd0 = p01.x, bd1 = p01.y, bd2 = p23.x, bd3 = p23.y;
#pragma unroll
            for (int i = 0; i < TM; i++) {
                ull ap = pack2(av[i]);
                dfma(acc2[i][0], ap, bd0);
                dfma(acc2[i][1], ap, bd1);
                dfma(acc2[i][2], ap, bd2);
                dfma(acc2[i][3], ap, bd3);
            }
        }
    }

    int nb = bn + tn;
    float colA[8];
    if (MODE == 0 || MODE == 1) {
#pragma unroll
        for (int j = 0; j < 8; j++) colA[j] = bias0[nb + j];
    } else if (MODE == 2) {
#pragma unroll
        for (int j = 0; j < 8; j++) { int p = permg(nb + j); colA[j] = bih[p] + bhh[p]; }
    } else if (MODE == 3) {
#pragma unroll
        for (int j = 0; j < 8; j++) colA[j] = vr[nb + j];
    }

#pragma unroll
    for (int i = 0; i < TM; i++) {
        size_t m = (size_t)(bm + tm + i);
        float v[8];
#pragma unroll
        for (int jp = 0; jp < 4; jp++) {
            float2 f = unpack2(acc2[i][jp]);
            v[2 * jp] = f.x; v[2 * jp + 1] = f.y;
        }
        if (MODE == 0) {
#pragma unroll
            for (int j = 0; j < 8; j++) v[j] = fmaxf(v[j] + colA[j], 0.f);
            float4* cp = (float4*)(C + m * N + nb);
            cp[0] = make_float4(v[0], v[1], v[2], v[3]);
            cp[1] = make_float4(v[4], v[5], v[6], v[7]);
        } else if (MODE == 1) {
            const float4* am = (const float4*)(addmat + m * N + nb);
            float4 m0 = am[0], m1 = am[1];
            v[0] += colA[0] + m0.x; v[1] += colA[1] + m0.y;
            v[2] += colA[2] + m0.z; v[3] += colA[3] + m0.w;
            v[4] += colA[4] + m1.x; v[5] += colA[5] + m1.y;
            v[6] += colA[6] + m1.z; v[7] += colA[7] + m1.w;
            float4* cp = (float4*)(C + m * N + nb);
            cp[0] = make_float4(v[0], v[1], v[2], v[3]);
            cp[1] = make_float4(v[4], v[5], v[6], v[7]);
        } else if (MODE == 4) {
            float4* cp = (float4*)(C + m * N + nb);
            cp[0] = make_float4(v[0], v[1], v[2], v[3]);
            cp[1] = make_float4(v[4], v[5], v[6], v[7]);
        } else if (MODE == 2) {
#pragma unroll
            for (int j = 0; j < 8; j++) { v[j] += colA[j]; qp[m * GATES + nb + j] = v[j]; }
#pragma unroll
            for (int h = 0; h < 2; h++) {
                int u = (nb >> 2) + h;
                const float* vv = v + h * 4;
                float cc = sigmf(vv[0]) * tanhf(vv[2]);
                cst[m * HID + u] = cc;
                if (nb < 1024)
                    hout[m * DM + u] = qg[m * DM + u] + sigmf(vv[3]) * tanhf(cc);
            }
        } else if (MODE == 3) {
            const float4* qm = (const float4*)(qp + m * GATES + nb);
            float4 q0 = qm[0], q1 = qm[1];
            v[0] += colA[0] + q0.x; v[1] += colA[1] + q0.y;
            v[2] += colA[2] + q0.z; v[3] += colA[3] + q0.w;
            v[4] += colA[4] + q1.x; v[5] += colA[5] + q1.y;
            v[6] += colA[6] + q1.z; v[7] += colA[7] + q1.w;
#pragma unroll
            for (int h = 0; h < 2; h++) {
                int u = (nb >> 2) + h;
                const float* vv = v + h * 4;
                float co = cst[m * HID + u];
                float cc = sigmf(vv[1]) * co + sigmf(vv[0]) * tanhf(vv[2]);
                cst[m * HID + u] = cc;
                if (nb < 1024)
                    hout[m * DM + u] = qg[m * DM + u] + sigmf(vv[3]) * tanhf(cc);
            }
        }
    }
}

// ---------------- support encoder (5 rows) + support_g + normalized sg ----------------
__global__ __launch_bounds__(256) void support_kernel(
    const float* __restrict__ p1_w, const float* __restrict__ p1_b,
    const float* __restrict__ p2_w, const float* __restrict__ p2_b,
    const float* __restrict__ ln_g, const float* __restrict__ ln_b)
{
    __shared__ float sx[DM], sh[HID], sz[DM];
    __shared__ float red[8];
    int tid = threadIdx.x, lane = tid & 31, wid = tid >> 5;
    float accg = 0.f;
    for (int r = 0; r < FEW; r++) {
        sx[tid] = g_sn[r * DM + tid];
        __syncthreads();
        for (int u = wid; u < HID; u += 8) {
            const float* w = p1_w + (size_t)u * DM;
            float a = 0.f;
#pragma unroll
            for (int s = 0; s < 8; s++) a += w[lane + 32 * s] * sx[lane + 32 * s];
            a = wred(a);
            if (lane == 0) sh[u] = fmaxf(a + p1_b[u], 0.f);
        }
        __syncthreads();
        for (int u = wid; u < DM; u += 8) {
            const float* w = p2_w + (size_t)u * HID;
            float a = 0.f;
#pragma unroll
            for (int s = 0; s < 16; s++) a += w[lane + 32 * s] * sh[lane + 32 * s];
            a = wred(a);
            if (lane == 0) sz[u] = a + p2_b[u] + sx[u];
        }
        __syncthreads();
        float z = sz[tid];
        float s1 = wred(z);
        if (lane == 0) red[wid] = s1;
        __syncthreads();
        float mu = (red[0] + red[1] + red[2] + red[3] + red[4] + red[5] + red[6] + red[7]) * (1.f / DM);
        __syncthreads();
        float dz = z - mu;
        float s2 = wred(dz * dz);
        if (lane == 0) red[wid] = s2;
        __syncthreads();
        float var = (red[0] + red[1] + red[2] + red[3] + red[4] + red[5] + red[6] + red[7]) * (1.f / (DM - 1));
        float sig = sqrtf(var);
        accg += dz / (sig + 1e-3f) * ln_g[tid] + ln_b[tid];
        __syncthreads();
    }
    float sg = accg * (1.f / FEW);
    g_sg[tid] = sg;
    float s3 = wred(sg * sg);
    if (lane == 0) red[wid] = s3;
    __syncthreads();
    float nrm = sqrtf(red[0] + red[1] + red[2] + red[3] + red[4] + red[5] + red[6] + red[7]);
    g_sgn[tid] = sg / fmaxf(nrm, 1e-12f);
}

// v_r permuted: g_vr[n] = support_g · w_hh[perm(n), 256:512]
__global__ __launch_bounds__(256) void vr_kernel(const float* __restrict__ w_hh) {
    int lane = threadIdx.x & 31, wid = threadIdx.x >> 5;
    int g = blockIdx.x * 8 + wid;
    int p = permg(g);
    const float* w = w_hh + (size_t)p * HID + DM;
    float a = 0.f;
#pragma unroll
    for (int s = 0; s < 8; s++) a += w[lane + 32 * s] * g_sg[lane + 32 * s];
    a = wred(a);
    if (lane == 0) g_vr[g] = a;
}

// layernorm over g_qg rows, in place
__global__ __launch_bounds__(256) void ln_kernel(const float* __restrict__ ln_g,
                                                 const float* __restrict__ ln_b) {
    __shared__ float red[8];
    int row = blockIdx.x, tid = threadIdx.x, lane = tid & 31, wid = tid >> 5;
    float z = g_qg[(size_t)row * DM + tid];
    float s1 = wred(z);
    if (lane == 0) red[wid] = s1;
    __syncthreads();
    float mu = (red[0] + red[1] + red[2] + red[3] + red[4] + red[5] + red[6] + red[7]) * (1.f / DM);
    __syncthreads();
    float dz = z - mu;
    float s2 = wred(dz * dz);
    if (lane == 0) red[wid] = s2;
    __syncthreads();
    float sig = sqrtf((red[0] + red[1] + red[2] + red[3] + red[4] + red[5] + red[6] + red[7]) * (1.f / (DM - 1)));
    g_qg[(size_t)row * DM + tid] = dz / (sig + 1e-3f) * ln_g[tid] + ln_b[tid];
}

// out[row] = (h / max(||h||,1e-12)) · sg_normalized
__global__ __launch_bounds__(256) void final_kernel(float* __restrict__ out) {
    int lane = threadIdx.x & 31, wid = threadIdx.x >> 5;
    int row = blockIdx.x * 8 + wid;
    const float* h = g_hb + (size_t)row * DM;
    float ss = 0.f, dt = 0.f;
#pragma unroll
    for (int s = 0; s < 8; s++) {
        float v = h[lane + 32 * s];
        ss += v * v;
        dt += v * g_sgn[lane + 32 * s];
    }
    ss = wred(ss); dt = wred(dt);
    if (lane == 0) out[row] = dt / fmaxf(sqrtf(ss), 1e-12f);
}

// ---------------- host ----------------
extern "C" void kernel_launch(void* const* d_in, const int* in_sizes, int n_in,
                              void* d_out, int out_size) {
    const int*   query   = (const int*)d_in[0];
    const int*   support = (const int*)d_in[1];
    const int*   qlc     = (const int*)d_in[2];
    const int*   qrc     = (const int*)d_in[4];
    const int*   slc     = (const int*)d_in[6];
    const int*   src_    = (const int*)d_in[8];
    const int*   knn     = (const int*)d_in[10];
    const float* emb     = (const float*)d_in[11];
    const float* gcn_w   = (const float*)d_in[12];
    const float* gcn_w_b = (const float*)d_in[13];
    const float* gcn_b   = (const float*)d_in[14];
    const float* gate_w  = (const float*)d_in[15];
    const float* gate_b  = (const float*)d_in[16];
    const float* p1_w    = (const float*)d_in[17];
    const float* p1_b    = (const float*)d_in[18];
    const float* p2_w    = (const float*)d_in[19];
    const float* p2_b    = (const float*)d_in[20];
    const float* ln_g    = (const float*)d_in[21];
    const float* ln_b    = (const float*)d_in[22];
    const float* w_ih    = (const float*)d_in[23];
    const float* w_hh    = (const float*)d_in[24];
    const float* b_ih    = (const float*)d_in[25];
    const float* b_hh    = (const float*)d_in[26];
    float* out = (float*)d_out;

    float *hs, *hk, *c1, *c2, *qn, *sn, *act, *qg, *vr, *qp, *cst, *ha, *hb;
    cudaGetSymbolAddress((void**)&hs, g_hs);
    cudaGetSymbolAddress((void**)&hk, g_hk);
    cudaGetSymbolAddress((void**)&c1, g_c1);
    cudaGetSymbolAddress((void**)&c2, g_c2);
    cudaGetSymbolAddress((void**)&qn, g_qn);
    cudaGetSymbolAddress((void**)&sn, g_sn);
    cudaGetSymbolAddress((void**)&act, g_act);
    cudaGetSymbolAddress((void**)&qg, g_qg);
    cudaGetSymbolAddress((void**)&vr, g_vr);
    cudaGetSymbolAddress((void**)&qp, g_qp);
    cudaGetSymbolAddress((void**)&cst, g_cst);
    cudaGetSymbolAddress((void**)&ha, g_ha);
    cudaGetSymbolAddress((void**)&hb, g_hb);

    // 1) gather + topk means
    neigh_gather<<<NTASK, 256>>>(query, support, qlc, qrc, slc, src_, knn, emb);
    // 2) dual GCN GEMM: c1 = hs @ gcn_wᵀ ; c2 = hk @ gcn_w[:,128:]ᵀ
    sgemm<64, 4><<<dim3(1, TPAD / 64, 2), 256>>>(
        hs, DM, gcn_w, DM, c1, D, DM,
        nullptr, nullptr, nullptr, nullptr, nullptr, nullptr, nullptr, nullptr, nullptr,
        hk, D, gcn_w + D, D, c2);
    // 3) tanh + gate + scatter
    combine_kernel<<<(NTASK + 7) / 8, 256>>>(gcn_w_b, gcn_b, gate_w, gate_b);
    // 4) support path
    support_kernel<<<1, 256>>>(p1_w, p1_b, p2_w, p2_b, ln_g, ln_b);
    vr_kernel<<<GATES / 8, 256>>>(w_hh);
    // 5) query support-encoder
    sgemm<64, 0><<<dim3(HID / 128, Bq / 64), 256>>>(
        qn, DM, p1_w, DM, act, HID, DM, p1_b,
        nullptr, nullptr, nullptr, nullptr, nullptr, nullptr, nullptr, nullptr,
        nullptr, 0, nullptr, 0, nullptr);
    sgemm<64, 1><<<dim3(DM / 128, Bq / 64), 256>>>(
        act, HID, p2_w, HID, qg, DM, HID, p2_b,
        qn, nullptr, nullptr, nullptr, nullptr, nullptr, nullptr, nullptr,
        nullptr, 0, nullptr, 0, nullptr);
    ln_kernel<<<Bq, 256>>>(ln_g, ln_b);
    // 6) LSTM: fused first step, then 3 fused recurrent steps (ping-pong h)
    sgemm<128, 2><<<dim3(GATES / 128, Bq / 128), 256>>>(
        qg, DM, w_ih, DM, nullptr, GATES, DM, nullptr, nullptr,
        qp, nullptr, b_ih, b_hh, cst, qg, ha,
        nullptr, 0, nullptr, 0, nullptr);
    sgemm<128, 3><<<dim3(GATES / 128, Bq / 128), 256>>>(
        ha, DM, w_hh, HID, nullptr, GATES, DM, nullptr, nullptr,
        qp, vr, nullptr, nullptr, cst, qg, hb,
        nullptr, 0, nullptr, 0, nullptr);
    sgemm<128, 3><<<dim3(GATES / 128, Bq / 128), 256>>>(
        hb, DM, w_hh, HID, nullptr, GATES, DM, nullptr, nullptr,
        qp, vr, nullptr, nullptr, cst, qg, ha,
        nullptr, 0, nullptr, 0, nullptr);
    sgemm<128, 3><<<dim3(GATES / 128, Bq / 128), 256>>>(
        ha, DM, w_hh, HID, nullptr, GATES, DM, nullptr, nullptr,
        qp, vr, nullptr, nullptr, cst, qg, hb,
        nullptr, 0, nullptr, 0, nullptr);
    // 7) normalized dot
    final_kernel<<<Bq / 8, 256>>>(out);
}

// round 3
// speedup vs baseline: 1.9676x; 1.4410x over previous
#include <cuda_runtime.h>
#include <math.h>

#define D     128
#define Mn    128
#define KTAB  64
#define KSEL  32
#define Bq    2048
#define FEW   5
#define DM    256
#define HID   512
#define GATES 2048
#define NTASK (2 * Bq + 2 * FEW)   // 4106
#define TPAD  4160                 // padded task rows for GEMM

typedef unsigned long long ull;

// ---------------- scratch (device globals; no allocation) ----------------
__device__ __align__(128) float g_hs[TPAD * DM];     // [rel_avg | ent_avg]
__device__ __align__(128) float g_hk[TPAD * D];      // knn ent avg
__device__ __align__(128) float g_c1[TPAD * D];      // struct pre-activation
__device__ __align__(128) float g_c2[TPAD * D];      // knn pre-activation
__device__ __align__(128) float g_qn[Bq * DM];
__device__ __align__(128) float g_sn[FEW * DM];
__device__ __align__(128) float g_sh[FEW * HID];
__device__ __align__(128) float g_sz[FEW * DM];
__device__ __align__(128) float g_act[Bq * HID];
__device__ __align__(128) float g_qg[Bq * DM];
__device__ __align__(128) float g_sg[DM];
__device__ __align__(128) float g_sgn[DM];
__device__ __align__(128) float g_vr[GATES];
__device__ __align__(128) float g_qp[(size_t)Bq * GATES];
__device__ __align__(128) float g_cst[Bq * HID];
__device__ __align__(128) float g_ha[Bq * DM];
__device__ __align__(128) float g_hb[Bq * DM];

__device__ __forceinline__ float wred(float v) {
#pragma unroll
    for (int o = 16; o; o >>= 1) v += __shfl_xor_sync(0xffffffffu, v, o);
    return v;
}
__device__ __forceinline__ float sigmf(float x) { return 1.f / (1.f + expf(-x)); }

__device__ __forceinline__ ull pack2(float x) {
    ull r;
    asm("mov.b64 %0, {%1, %1};" : "=l"(r) : "r"(__float_as_uint(x)));
    return r;
}
__device__ __forceinline__ void dfma(ull& d, ull a, ull b) {
    asm("fma.rn.f32x2 %0, %1, %2, %0;" : "+l"(d) : "l"(a), "l"(b));
}
__device__ __forceinline__ float2 unpack2(ull v) {
    unsigned lo, hi;
    asm("mov.b64 {%0, %1}, %2;" : "=r"(lo), "=r"(hi) : "l"(v));
    float2 f; f.x = __uint_as_float(lo); f.y = __uint_as_float(hi);
    return f;
}
__device__ __forceinline__ int permg(int n) { return (n & 3) * 512 + (n >> 2); }

// ---------------- neighbor gather: sims + topk + selected means ----------------
__global__ __launch_bounds__(256) void neigh_gather(
    const int* __restrict__ query, const int* __restrict__ support,
    const int* __restrict__ qlc, const int* __restrict__ qrc,
    const int* __restrict__ slc, const int* __restrict__ src_,
    const int* __restrict__ knn, const float* __restrict__ emb)
{
    __shared__ float s_center[D];
    __shared__ int   s_rid[Mn], s_eid[Mn];
    __shared__ float s_sim[Mn];
    __shared__ int   s_kid[KTAB];
    __shared__ float s_ksim[KTAB];
    __shared__ int   s_selr[KSEL], s_sele[KSEL], s_kselv[KSEL];
    __shared__ int   s_cnt, s_kcnt;
    __shared__ float s_cn;

    int task = blockIdx.x;
    const int* conn; int id;
    if (task < 2 * Bq) {
        int row = task & (Bq - 1);
        int br  = task >> 11;
        conn = (br ? qrc : qlc) + (size_t)row * Mn * 2;
        id   = query[row * 2 + br];
    } else {
        int t = task - 2 * Bq;
        int br = t / FEW, row = t % FEW;
        conn = (br ? src_ : slc) + (size_t)row * Mn * 2;
        id   = support[row * 2 + br];
    }
    int tid = threadIdx.x, lane = tid & 31, wid = tid >> 5;
    if (tid == 0) { s_cnt = 0; s_kcnt = 0; }
    if (tid < D)  s_center[tid] = emb[(size_t)id * D + tid];
    if (tid < Mn) { s_rid[tid] = conn[tid * 2]; s_eid[tid] = conn[tid * 2 + 1]; }
    if (tid >= 192) s_kid[tid - 192] = knn[(size_t)id * KTAB + (tid - 192)];
    __syncthreads();

    if (wid == 0) {
        float c0 = s_center[lane], c1 = s_center[lane + 32],
              c2 = s_center[lane + 64], c3 = s_center[lane + 96];
        float s = wred(c0 * c0 + c1 * c1 + c2 * c2 + c3 * c3);
        if (lane == 0) s_cn = sqrtf(s);
    }
    __syncthreads();
    float cn = s_cn;
    float4 cv = ((const float4*)s_center)[lane];

    // ent sims: warp handles 16 m, groups of 4 with interleaved reductions
#pragma unroll
    for (int g = 0; g < 4; g++) {
        int m = wid * 16 + g * 4;
        float dt[4], nn[4];
#pragma unroll
        for (int t = 0; t < 4; t++) {
            float4 ev = ((const float4*)(emb + (size_t)s_eid[m + t] * D))[lane];
            dt[t] = ev.x * cv.x + ev.y * cv.y + ev.z * cv.z + ev.w * cv.w;
            nn[t] = ev.x * ev.x + ev.y * ev.y + ev.z * ev.z + ev.w * ev.w;
        }
#pragma unroll
        for (int o = 16; o; o >>= 1) {
#pragma unroll
            for (int t = 0; t < 4; t++) {
                dt[t] += __shfl_xor_sync(0xffffffffu, dt[t], o);
                nn[t] += __shfl_xor_sync(0xffffffffu, nn[t], o);
            }
        }
        if (lane == 0) {
#pragma unroll
            for (int t = 0; t < 4; t++)
                s_sim[m + t] = dt[t] / fmaxf(cn * sqrtf(nn[t]), 1e-8f);
        }
    }
    // knn sims: warp handles 8
#pragma unroll
    for (int g = 0; g < 2; g++) {
        int m = wid * 8 + g * 4;
        float dt[4], nn[4];
#pragma unroll
        for (int t = 0; t < 4; t++) {
            float4 ev = ((const float4*)(emb + (size_t)s_kid[m + t] * D))[lane];
            dt[t] = ev.x * cv.x + ev.y * cv.y + ev.z * cv.z + ev.w * cv.w;
            nn[t] = ev.x * ev.x + ev.y * ev.y + ev.z * ev.z + ev.w * ev.w;
        }
#pragma unroll
        for (int o = 16; o; o >>= 1) {
#pragma unroll
            for (int t = 0; t < 4; t++) {
                dt[t] += __shfl_xor_sync(0xffffffffu, dt[t], o);
                nn[t] += __shfl_xor_sync(0xffffffffu, nn[t], o);
            }
        }
        if (lane == 0) {
#pragma unroll
            for (int t = 0; t < 4; t++)
                s_ksim[m + t] = dt[t] / fmaxf(cn * sqrtf(nn[t]), 1e-8f);
        }
    }
    __syncthreads();

    // exact top-K sets (jax tie semantics: lower index wins) + compaction
    if (tid < Mn) {
        float v = s_sim[tid]; int r = 0;
        for (int j = 0; j < Mn; j++) {
            float u = s_sim[j];
            r += (u > v) || (u == v && j < tid);
        }
        if (r < KSEL) {
            int p = atomicAdd(&s_cnt, 1);
            s_selr[p] = s_rid[tid];
            s_sele[p] = s_eid[tid];
        }
    } else if (tid < Mn + KTAB) {
        int m = tid - Mn;
        float v = s_ksim[m]; int r = 0;
        for (int j = 0; j < KTAB; j++) {
            float u = s_ksim[j];
            r += (u > v) || (u == v && j < m);
        }
        if (r < KSEL) {
            int p = atomicAdd(&s_kcnt, 1);
            s_kselv[p] = s_kid[m];
        }
    }
    __syncthreads();

    // means of selected rows (unrolled, full MLP)
    int d = tid & (D - 1);
    float acc = 0.f;
    if (tid < D) {
#pragma unroll 8
        for (int i = 0; i < KSEL; i++) acc += emb[(size_t)s_selr[i] * D + d];
        g_hs[(size_t)task * DM + d] = acc * (1.f / KSEL);
        float ak = 0.f;
#pragma unroll 8
        for (int i = 0; i < KSEL; i++) ak += emb[(size_t)s_kselv[i] * D + d];
        g_hk[(size_t)task * D + d] = ak * (1.f / KSEL);
    } else {
#pragma unroll 8
        for (int i = 0; i < KSEL; i++) acc += emb[(size_t)s_sele[i] * D + d];
        g_hs[(size_t)task * DM + D + d] = acc * (1.f / KSEL);
    }
}

// ---------------- combine: tanh + gate + scatter to qn/sn ----------------
__global__ __launch_bounds__(256) void combine_kernel(
    const float* __restrict__ gcn_w_b, const float* __restrict__ gcn_b,
    const float* __restrict__ gate_w, const float* __restrict__ gate_b)
{
    int lane = threadIdx.x & 31, wid = threadIdx.x >> 5;
    int t = blockIdx.x * 8 + wid;
    if (t >= NTASK) return;
    int c = lane * 4;
    float4 c1 = *(const float4*)(g_c1 + (size_t)t * D + c);
    float4 c2 = *(const float4*)(g_c2 + (size_t)t * D + c);
    float4 wb = *(const float4*)(gcn_w_b + c);
    float4 gb = *(const float4*)(gcn_b + c);
    float s0 = tanhf(c1.x + wb.x + gb.x), s1 = tanhf(c1.y + wb.y + gb.y);
    float s2 = tanhf(c1.z + wb.z + gb.z), s3 = tanhf(c1.w + wb.w + gb.w);
    float k0 = tanhf(c2.x + wb.x + gb.x), k1 = tanhf(c2.y + wb.y + gb.y);
    float k2 = tanhf(c2.z + wb.z + gb.z), k3 = tanhf(c2.w + wb.w + gb.w);
    float4 gws = *(const float4*)(gate_w + c);
    float4 gwk = *(const float4*)(gate_w + D + c);
    float a = gws.x * s0 + gws.y * s1 + gws.z * s2 + gws.w * s3
            + gwk.x * k0 + gwk.y * k1 + gwk.z * k2 + gwk.w * k3;
    a = wred(a);
    float al = sigmf(a + gate_b[0]);
    float4 o;
    o.x = (1.f - al) * s0 + al * k0;
    o.y = (1.f - al) * s1 + al * k1;
    o.z = (1.f - al) * s2 + al * k2;
    o.w = (1.f - al) * s3 + al * k3;
    float* dst;
    if (t < Bq)            dst = g_qn + (size_t)t * DM + c;
    else if (t < 2 * Bq)   dst = g_qn + (size_t)(t - Bq) * DM + D + c;
    else if (t < 2 * Bq + FEW) dst = g_sn + (size_t)(t - 2 * Bq) * DM + c;
    else                   dst = g_sn + (size_t)(t - 2 * Bq - FEW) * DM + D + c;
    *(float4*)dst = o;
}

// ---------------- templated FFMA2 SGEMM: C[M,N] = A[M,K] · B[N,K]ᵀ ----------------
template<int BM, int MODE>
__global__ __launch_bounds__(256) void sgemm(
    const float* __restrict__ A, int lda,
    const float* __restrict__ B, int ldb,
    float* __restrict__ C, int N, int K,
    const float* __restrict__ bias0,
    const float* __restrict__ addmat,
    float* __restrict__ qp, const float* __restrict__ vr,
    const float* __restrict__ bih, const float* __restrict__ bhh,
    float* __restrict__ cst, const float* __restrict__ qg,
    float* __restrict__ hout,
    const float* __restrict__ A2, int lda2,
    const float* __restrict__ B2, int K2, float* __restrict__ C2)
{
    if (MODE == 4 && blockIdx.z == 1) { A = A2; lda = lda2; B = B2; K = K2; C = C2; }
    constexpr int TM = BM / 16;
    __shared__ float As[16][BM + 4];
    __shared__ float Bs[16][132];
    int tid = threadIdx.x;
    int bm = blockIdx.y * BM, bn = blockIdx.x * 128;
    int tm = (tid >> 4) * TM, tn = (tid & 15) * 8;
    int ar = tid >> 2, ac = (tid & 3) * 4;

    int br0 = bn + ar, br1 = bn + ar + 64;
    if (MODE == 2 || MODE == 3) { br0 = permg(br0); br1 = permg(br1); }
    const float* Ap  = A + (size_t)(bm + ar) * lda + ac;
    const float* Bp0 = B + (size_t)br0 * ldb + ac;
    const float* Bp1 = B + (size_t)br1 * ldb + ac;

    ull acc2[TM][4];
#pragma unroll
    for (int i = 0; i < TM; i++)
#pragma unroll
        for (int j = 0; j < 4; j++) acc2[i][j] = 0ULL;

    for (int k0 = 0; k0 < K; k0 += 16) {
        float4 a0 = *(const float4*)(Ap + k0);
        float4 a1;
        if (BM == 128) a1 = *(const float4*)(Ap + (size_t)64 * lda + k0);
        float4 b0 = *(const float4*)(Bp0 + k0);
        float4 b1 = *(const float4*)(Bp1 + k0);
        __syncthreads();
        As[ac + 0][ar] = a0.x; As[ac + 1][ar] = a0.y; As[ac + 2][ar] = a0.z; As[ac + 3][ar] = a0.w;
        if (BM == 128) {
            As[ac + 0][ar + 64] = a1.x; As[ac + 1][ar + 64] = a1.y;
            As[ac + 2][ar + 64] = a1.z; As[ac + 3][ar + 64] = a1.w;
        }
        Bs[ac + 0][ar] = b0.x; Bs[ac + 1][ar] = b0.y; Bs[ac + 2][ar] = b0.z; Bs[ac + 3][ar] = b0.w;
        Bs[ac + 0][ar + 64] = b1.x; Bs[ac + 1][ar + 64] = b1.y;
        Bs[ac + 2][ar + 64] = b1.z; Bs[ac + 3][ar + 64] = b1.w;
        __syncthreads();
#pragma unroll
        for (int kk = 0; kk < 16; kk++) {
            float av[TM];
            *(float4*)av = *(const float4*)&As[kk][tm];
            if (TM == 8) *(float4*)(av + 4) = *(const float4*)&As[kk][tm + 4];
            ulonglong2 p01 = *(const ulonglong2*)&Bs[kk][tn];
            ulonglong2 p23 = *(const ulonglong2*)&Bs[kk][tn + 4];
            ull bd0 = p01.x, bd1 = p01.y, bd2 = p23.x, bd3 = p23.y;
#pragma unroll
            for (int i = 0; i < TM; i++) {
                ull ap = pack2(av[i]);
                dfma(acc2[i][0], ap, bd0);
                dfma(acc2[i][1], ap, bd1);
                dfma(acc2[i][2], ap, bd2);
                dfma(acc2[i][3], ap, bd3);
            }
        }
    }

    int nb = bn + tn;
    float colA[8];
    if (MODE == 0 || MODE == 1) {
#pragma unroll
        for (int j = 0; j < 8; j++) colA[j] = bias0[nb + j];
    } else if (MODE == 2) {
#pragma unroll
        for (int j = 0; j < 8; j++) { int p = permg(nb + j); colA[j] = bih[p] + bhh[p]; }
    } else if (MODE == 3) {
#pragma unroll
        for (int j = 0; j < 8; j++) colA[j] = vr[nb + j];
    }

#pragma unroll
    for (int i = 0; i < TM; i++) {
        size_t m = (size_t)(bm + tm + i);
        float v[8];
#pragma unroll
        for (int jp = 0; jp < 4; jp++) {
            float2 f = unpack2(acc2[i][jp]);
            v[2 * jp] = f.x; v[2 * jp + 1] = f.y;
        }
        if (MODE == 0) {
#pragma unroll
            for (int j = 0; j < 8; j++) v[j] = fmaxf(v[j] + colA[j], 0.f);
            float4* cp = (float4*)(C + m * N + nb);
            cp[0] = make_float4(v[0], v[1], v[2], v[3]);
            cp[1] = make_float4(v[4], v[5], v[6], v[7]);
        } else if (MODE == 1) {
            const float4* am = (const float4*)(addmat + m * N + nb);
            float4 m0 = am[0], m1 = am[1];
            v[0] += colA[0] + m0.x; v[1] += colA[1] + m0.y;
            v[2] += colA[2] + m0.z; v[3] += colA[3] + m0.w;
            v[4] += colA[4] + m1.x; v[5] += colA[5] + m1.y;
            v[6] += colA[6] + m1.z; v[7] += colA[7] + m1.w;
            float4* cp = (float4*)(C + m * N + nb);
            cp[0] = make_float4(v[0], v[1], v[2], v[3]);
            cp[1] = make_float4(v[4], v[5], v[6], v[7]);
        } else if (MODE == 4) {
            float4* cp = (float4*)(C + m * N + nb);
            cp[0] = make_float4(v[0], v[1], v[2], v[3]);
            cp[1] = make_float4(v[4], v[5], v[6], v[7]);
        } else if (MODE == 2) {
#pragma unroll
            for (int j = 0; j < 8; j++) { v[j] += colA[j]; qp[m * GATES + nb + j] = v[j]; }
#pragma unroll
            for (int h = 0; h < 2; h++) {
                int u = (nb >> 2) + h;
                const float* vv = v + h * 4;
                float cc = sigmf(vv[0]) * tanhf(vv[2]);
                cst[m * HID + u] = cc;
                if (nb < 1024)
                    hout[m * DM + u] = qg[m * DM + u] + sigmf(vv[3]) * tanhf(cc);
            }
        } else if (MODE == 3) {
            const float4* qm = (const float4*)(qp + m * GATES + nb);
            float4 q0 = qm[0], q1 = qm[1];
            v[0] += colA[0] + q0.x; v[1] += colA[1] + q0.y;
            v[2] += colA[2] + q0.z; v[3] += colA[3] + q0.w;
            v[4] += colA[4] + q1.x; v[5] += colA[5] + q1.y;
            v[6] += colA[6] + q1.z; v[7] += colA[7] + q1.w;
#pragma unroll
            for (int h = 0; h < 2; h++) {
                int u = (nb >> 2) + h;
                const float* vv = v + h * 4;
                float co = cst[m * HID + u];
                float cc = sigmf(vv[1]) * co + sigmf(vv[0]) * tanhf(vv[2]);
                cst[m * HID + u] = cc;
                if (nb < 1024)
                    hout[m * DM + u] = qg[m * DM + u] + sigmf(vv[3]) * tanhf(cc);
            }
        }
    }
}

// ---------------- support encoder, parallel ----------------
// p1: 2560 warp-dots (5 rows × 512 units)
__global__ __launch_bounds__(256) void sup1_kernel(
    const float* __restrict__ p1_w, const float* __restrict__ p1_b)
{
    int lane = threadIdx.x & 31, wid = threadIdx.x >> 5;
    int w = blockIdx.x * 8 + wid;
    int r = w >> 9, u = w & (HID - 1);
    const float* wp = p1_w + (size_t)u * DM;
    const float* xp = g_sn + r * DM;
    float a = 0.f;
#pragma unroll
    for (int s = 0; s < 8; s++) a += wp[lane + 32 * s] * xp[lane + 32 * s];
    a = wred(a);
    if (lane == 0) g_sh[r * HID + u] = fmaxf(a + p1_b[u], 0.f);
}

// p2: 1280 warp-dots (5 rows × 256 units), + bias + residual
__global__ __launch_bounds__(256) void sup2_kernel(
    const float* __restrict__ p2_w, const float* __restrict__ p2_b)
{
    int lane = threadIdx.x & 31, wid = threadIdx.x >> 5;
    int w = blockIdx.x * 8 + wid;
    int r = w >> 8, u = w & (DM - 1);
    const float* wp = p2_w + (size_t)u * HID;
    const float* xp = g_sh + r * HID;
    float a = 0.f;
#pragma unroll
    for (int s = 0; s < 16; s++) a += wp[lane + 32 * s] * xp[lane + 32 * s];
    a = wred(a);
    if (lane == 0) g_sz[r * DM + u] = a + p2_b[u] + g_sn[r * DM + u];
}

// LN over 5 rows + mean + normalize (tiny)
__global__ __launch_bounds__(256) void sup3_kernel(
    const float* __restrict__ ln_g, const float* __restrict__ ln_b)
{
    __shared__ float red[8];
    int tid = threadIdx.x, lane = tid & 31, wid = tid >> 5;
    float accg = 0.f;
    for (int r = 0; r < FEW; r++) {
        float z = g_sz[r * DM + tid];
        float s1 = wred(z);
        if (lane == 0) red[wid] = s1;
        __syncthreads();
        float mu = (red[0] + red[1] + red[2] + red[3] + red[4] + red[5] + red[6] + red[7]) * (1.f / DM);
        __syncthreads();
        float dz = z - mu;
        float s2 = wred(dz * dz);
        if (lane == 0) red[wid] = s2;
        __syncthreads();
        float sig = sqrtf((red[0] + red[1] + red[2] + red[3] + red[4] + red[5] + red[6] + red[7]) * (1.f / (DM - 1)));
        accg += dz / (sig + 1e-3f) * ln_g[tid] + ln_b[tid];
        __syncthreads();
    }
    float sg = accg * (1.f / FEW);
    g_sg[tid] = sg;
    float s3 = wred(sg * sg);
    if (lane == 0) red[wid] = s3;
    __syncthreads();
    float nrm = sqrtf(red[0] + red[1] + red[2] + red[3] + red[4] + red[5] + red[6] + red[7]);
    g_sgn[tid] = sg / fmaxf(nrm, 1e-12f);
}

// v_r permuted: g_vr[n] = support_g · w_hh[perm(n), 256:512]
__global__ __launch_bounds__(256) void vr_kernel(const float* __restrict__ w_hh) {
    int lane = threadIdx.x & 31, wid = threadIdx.x >> 5;
    int g = blockIdx.x * 8 + wid;
    int p = permg(g);
    const float* w = w_hh + (size_t)p * HID + DM;
    float a = 0.f;
#pragma unroll
    for (int s = 0; s < 8; s++) a += w[lane + 32 * s] * g_sg[lane + 32 * s];
    a = wred(a);
    if (lane == 0) g_vr[g] = a;
}

// layernorm over g_qg rows, in place
__global__ __launch_bounds__(256) void ln_kernel(const float* __restrict__ ln_g,
                                                 const float* __restrict__ ln_b) {
    __shared__ float red[8];
    int row = blockIdx.x, tid = threadIdx.x, lane = tid & 31, wid = tid >> 5;
    float z = g_qg[(size_t)row * DM + tid];
    float s1 = wred(z);
    if (lane == 0) red[wid] = s1;
    __syncthreads();
    float mu = (red[0] + red[1] + red[2] + red[3] + red[4] + red[5] + red[6] + red[7]) * (1.f / DM);
    __syncthreads();
    float dz = z - mu;
    float s2 = wred(dz * dz);
    if (lane == 0) red[wid] = s2;
    __syncthreads();
    float sig = sqrtf((red[0] + red[1] + red[2] + red[3] + red[4] + red[5] + red[6] + red[7]) * (1.f / (DM - 1)));
    g_qg[(size_t)row * DM + tid] = dz / (sig + 1e-3f) * ln_g[tid] + ln_b[tid];
}

// out[row] = (h / max(||h||,1e-12)) · sg_normalized
__global__ __launch_bounds__(256) void final_kernel(float* __restrict__ out) {
    int lane = threadIdx.x & 31, wid = threadIdx.x >> 5;
    int row = blockIdx.x * 8 + wid;
    const float* h = g_hb + (size_t)row * DM;
    float ss = 0.f, dt = 0.f;
#pragma unroll
    for (int s = 0; s < 8; s++) {
        float v = h[lane + 32 * s];
        ss += v * v;
        dt += v * g_sgn[lane + 32 * s];
    }
    ss = wred(ss); dt = wred(dt);
    if (lane == 0) out[row] = dt / fmaxf(sqrtf(ss), 1e-12f);
}

// ---------------- host ----------------
extern "C" void kernel_launch(void* const* d_in, const int* in_sizes, int n_in,
                              void* d_out, int out_size) {
    const int*   query   = (const int*)d_in[0];
    const int*   support = (const int*)d_in[1];
    const int*   qlc     = (const int*)d_in[2];
    const int*   qrc     = (const int*)d_in[4];
    const int*   slc     = (const int*)d_in[6];
    const int*   src_    = (const int*)d_in[8];
    const int*   knn     = (const int*)d_in[10];
    const float* emb     = (const float*)d_in[11];
    const float* gcn_w   = (const float*)d_in[12];
    const float* gcn_w_b = (const float*)d_in[13];
    const float* gcn_b   = (const float*)d_in[14];
    const float* gate_w  = (const float*)d_in[15];
    const float* gate_b  = (const float*)d_in[16];
    const float* p1_w    = (const float*)d_in[17];
    const float* p1_b    = (const float*)d_in[18];
    const float* p2_w    = (const float*)d_in[19];
    const float* p2_b    = (const float*)d_in[20];
    const float* ln_g    = (const float*)d_in[21];
    const float* ln_b    = (const float*)d_in[22];
    const float* w_ih    = (const float*)d_in[23];
    const float* w_hh    = (const float*)d_in[24];
    const float* b_ih    = (const float*)d_in[25];
    const float* b_hh    = (const float*)d_in[26];
    float* out = (float*)d_out;

    float *hs, *hk, *c1, *c2, *qn, *act, *qg, *vr, *qp, *cst, *ha, *hb;
    cudaGetSymbolAddress((void**)&hs, g_hs);
    cudaGetSymbolAddress((void**)&hk, g_hk);
    cudaGetSymbolAddress((void**)&c1, g_c1);
    cudaGetSymbolAddress((void**)&c2, g_c2);
    cudaGetSymbolAddress((void**)&qn, g_qn);
    cudaGetSymbolAddress((void**)&act, g_act);
    cudaGetSymbolAddress((void**)&qg, g_qg);
    cudaGetSymbolAddress((void**)&vr, g_vr);
    cudaGetSymbolAddress((void**)&qp, g_qp);
    cudaGetSymbolAddress((void**)&cst, g_cst);
    cudaGetSymbolAddress((void**)&ha, g_ha);
    cudaGetSymbolAddress((void**)&hb, g_hb);

    // 1) gather + topk means
    neigh_gather<<<NTASK, 256>>>(query, support, qlc, qrc, slc, src_, knn, emb);
    // 2) dual GCN GEMM: c1 = hs @ gcn_wᵀ ; c2 = hk @ gcn_w[:,128:]ᵀ
    sgemm<64, 4><<<dim3(1, TPAD / 64, 2), 256>>>(
        hs, DM, gcn_w, DM, c1, D, DM,
        nullptr, nullptr, nullptr, nullptr, nullptr, nullptr, nullptr, nullptr, nullptr,
        hk, D, gcn_w + D, D, c2);
    // 3) tanh + gate + scatter
    combine_kernel<<<(NTASK + 7) / 8, 256>>>(gcn_w_b, gcn_b, gate_w, gate_b);
    // 4) support path (parallel)
    sup1_kernel<<<FEW * HID / 8, 256>>>(p1_w, p1_b);
    sup2_kernel<<<FEW * DM / 8, 256>>>(p2_w, p2_b);
    sup3_kernel<<<1, 256>>>(ln_g, ln_b);
    vr_kernel<<<GATES / 8, 256>>>(w_hh);
    // 5) query support-encoder
    sgemm<64, 0><<<dim3(HID / 128, Bq / 64), 256>>>(
        qn, DM, p1_w, DM, act, HID, DM, p1_b,
        nullptr, nullptr, nullptr, nullptr, nullptr, nullptr, nullptr, nullptr,
        nullptr, 0, nullptr, 0, nullptr);
    sgemm<64, 1><<<dim3(DM / 128, Bq / 64), 256>>>(
        act, HID, p2_w, HID, qg, DM, HID, p2_b,
        qn, nullptr, nullptr, nullptr, nullptr, nullptr, nullptr, nullptr,
        nullptr, 0, nullptr, 0, nullptr);
    ln_kernel<<<Bq, 256>>>(ln_g, ln_b);
    // 6) LSTM: fused first step, then 3 fused recurrent steps (ping-pong h)
    sgemm<128, 2><<<dim3(GATES / 128, Bq / 128), 256>>>(
        qg, DM, w_ih, DM, nullptr, GATES, DM, nullptr, nullptr,
        qp, nullptr, b_ih, b_hh, cst, qg, ha,
        nullptr, 0, nullptr, 0, nullptr);
    sgemm<128, 3><<<dim3(GATES / 128, Bq / 128), 256>>>(
        ha, DM, w_hh, HID, nullptr, GATES, DM, nullptr, nullptr,
        qp, vr, nullptr, nullptr, cst, qg, hb,
        nullptr, 0, nullptr, 0, nullptr);
    sgemm<128, 3><<<dim3(GATES / 128, Bq / 128), 256>>>(
        hb, DM, w_hh, HID, nullptr, GATES, DM, nullptr, nullptr,
        qp, vr, nullptr, nullptr, cst, qg, ha,
        nullptr, 0, nullptr, 0, nullptr);
    sgemm<128, 3><<<dim3(GATES / 128, Bq / 128), 256>>>(
        ha, DM, w_hh, HID, nullptr, GATES, DM, nullptr, nullptr,
        qp, vr, nullptr, nullptr, cst, qg, hb,
        nullptr, 0, nullptr, 0, nullptr);
    // 7) normalized dot
    final_kernel<<<Bq / 8, 256>>>(out);
}